// round 15
// baseline (speedup 1.0000x reference)
#include <cuda_runtime.h>
#include <cooperative_groups.h>
#include <cstdint>

namespace cg = cooperative_groups;

#define NB    16
#define NPTS  65536
#define NSEED 40
#define RAD2  0.0025f

#define FPS_CL 8
#define FPS_T  1024
#define FPS_PT 8                 // NPTS / (FPS_CL * FPS_T)
#define FPS_PR (FPS_PT / 2)

#define DEN_T      256
#define DEN_PT     8             // consecutive points per thread
#define DEN_PRR    (DEN_PT / 2)
#define DEN_CHUNKS (NPTS / (DEN_T * DEN_PT))   // 32
#define DEN_CTAS   (DEN_CHUNKS * NB)           // 512

__device__ float g_seeds[NB * NSEED * 3];
__device__ __align__(16) float g_den[NB * NSEED];
__device__ unsigned g_done;

// ---------------- f32x2 packed helpers (element-wise rn => bitwise == scalar)
__device__ __forceinline__ uint64_t pack2(float lo, float hi) {
    uint64_t r; asm("mov.b64 %0, {%1, %2};" : "=l"(r) : "f"(lo), "f"(hi)); return r;
}
__device__ __forceinline__ void unpack2(uint64_t v, float& lo, float& hi) {
    asm("mov.b64 {%0, %1}, %2;" : "=f"(lo), "=f"(hi) : "l"(v));
}
__device__ __forceinline__ uint64_t add2(uint64_t a, uint64_t b) {
    uint64_t r; asm("add.rn.f32x2 %0, %1, %2;" : "=l"(r) : "l"(a), "l"(b)); return r;
}
__device__ __forceinline__ uint64_t mul2(uint64_t a, uint64_t b) {
    uint64_t r; asm("mul.rn.f32x2 %0, %1, %2;" : "=l"(r) : "l"(a), "l"(b)); return r;
}
__device__ __forceinline__ uint64_t fma2(uint64_t a, uint64_t b, uint64_t c) {
    uint64_t r; asm("fma.rn.f32x2 %0, %1, %2, %3;" : "=l"(r) : "l"(a), "l"(b), "l"(c)); return r;
}

// ---------------- cluster / mbarrier helpers
__device__ __forceinline__ uint32_t ctarank() {
    uint32_t r; asm("mov.u32 %0, %%cluster_ctarank;" : "=r"(r)); return r;
}
__device__ __forceinline__ uint32_t mapa_u32(uint32_t sa, uint32_t rank) {
    uint32_t r; asm("mapa.shared::cluster.u32 %0, %1, %2;" : "=r"(r) : "r"(sa), "r"(rank));
    return r;
}
__device__ __forceinline__ void st_cluster_v4(uint32_t a, uint32_t x, uint32_t y,
                                              uint32_t z, uint32_t w) {
    asm volatile("st.shared::cluster.v4.b32 [%0], {%1,%2,%3,%4};"
                 :: "r"(a), "r"(x), "r"(y), "r"(z), "r"(w) : "memory");
}
__device__ __forceinline__ void st_cluster_b32(uint32_t a, uint32_t v) {
    asm volatile("st.shared::cluster.b32 [%0], %1;" :: "r"(a), "r"(v) : "memory");
}
__device__ __forceinline__ void mbar_init(uint32_t a, uint32_t cnt) {
    asm volatile("mbarrier.init.shared.b64 [%0], %1;" :: "r"(a), "r"(cnt) : "memory");
}
__device__ __forceinline__ void mbar_arrive_rel_cluster(uint32_t a) {
    asm volatile("mbarrier.arrive.release.cluster.shared::cluster.b64 _, [%0];"
                 :: "r"(a) : "memory");
}
__device__ __forceinline__ void mbar_wait_acq_cluster(uint32_t a, uint32_t parity) {
    asm volatile(
        "{\n\t.reg .pred P;\n\t"
        "WL_%=:\n\t"
        "mbarrier.try_wait.parity.acquire.cluster.shared::cta.b64 P, [%0], %1, 0x989680;\n\t"
        "@!P bra WL_%=;\n\t"
        "}" :: "r"(a), "r"(parity) : "memory");
}
__device__ __forceinline__ void cluster_sync_all() {
    asm volatile("barrier.cluster.arrive.aligned;" ::: "memory");
    asm volatile("barrier.cluster.wait.aligned;" ::: "memory");
}

// ---------------------------------------------------------------------------
// Kernel 1: farthest point sampling — the best-measured (R2/R10/R14,
// 103-104us) protocol, byte-identical except one added g_done reset.
// 8-CTA cluster per batch, 1024 thr/CTA, 8 pts/thread register-resident
// packed f32x2 (element-wise rn => bitwise == reference scalar order).
// Tie-break: u64 key (distbits<<32)|~gi, max => first index == jnp.argmax.
// ---------------------------------------------------------------------------
__global__ void __cluster_dims__(FPS_CL, 1, 1) __launch_bounds__(FPS_T, 1)
fps_kernel(const float* __restrict__ pcs)
{
    const uint32_t rank = ctarank();
    const int batch = blockIdx.x / FPS_CL;
    const int t = threadIdx.x;
    const int warp = t >> 5, lane = t & 31;

    __shared__ float s_warp[32];
    __shared__ unsigned s_idx;
    __shared__ float s_cand[3];
    __shared__ float s_cent[3];
    __shared__ __align__(16) uint4 s_slot4[2][FPS_CL];   // {distbits, gi, xbits, ybits}
    __shared__ float s_slotz[2][FPS_CL];
    __shared__ __align__(8) unsigned long long s_mbar[2];

    const float* base = pcs + (size_t)batch * NPTS * 3;
    const int gi0 = (int)rank * (FPS_T * FPS_PT) + t;

    // load points, pack pairs (2j, 2j+1)
    float lx[FPS_PT], ly[FPS_PT], lz[FPS_PT];
#pragma unroll
    for (int i = 0; i < FPS_PT; i++) {
        const int gi = gi0 + i * FPS_T;
        lx[i] = base[gi * 3 + 0];
        ly[i] = base[gi * 3 + 1];
        lz[i] = base[gi * 3 + 2];
    }
    uint64_t PX[FPS_PR], PY[FPS_PR], PZ[FPS_PR];
    float dist[FPS_PT];
#pragma unroll
    for (int j = 0; j < FPS_PR; j++) {
        PX[j] = pack2(lx[2 * j], lx[2 * j + 1]);
        PY[j] = pack2(ly[2 * j], ly[2 * j + 1]);
        PZ[j] = pack2(lz[2 * j], lz[2 * j + 1]);
    }
#pragma unroll
    for (int i = 0; i < FPS_PT; i++) dist[i] = 1e10f;

    if (t == 0) {
        mbar_init((uint32_t)__cvta_generic_to_shared(&s_mbar[0]), FPS_CL);
        mbar_init((uint32_t)__cvta_generic_to_shared(&s_mbar[1]), FPS_CL);
        s_cent[0] = base[0]; s_cent[1] = base[1]; s_cent[2] = base[2];
    }
    if (rank == 0) {
        if (t < NSEED) g_den[batch * NSEED + t] = 0.0f;
        if (t == 0) {
            g_seeds[(batch * NSEED) * 3 + 0] = base[0];
            g_seeds[(batch * NSEED) * 3 + 1] = base[1];
            g_seeds[(batch * NSEED) * 3 + 2] = base[2];
            if (batch == 0) g_done = 0;
        }
    }
    __syncthreads();
    cluster_sync_all();   // all mbarriers initialized cluster-wide

#pragma unroll 1
    for (int k = 0; k < NSEED - 1; k++) {
        const float cx = s_cent[0], cy = s_cent[1], cz = s_cent[2];
        const uint64_t ncx2 = pack2(-cx, -cx);
        const uint64_t ncy2 = pack2(-cy, -cy);
        const uint64_t ncz2 = pack2(-cz, -cz);

        // ---- packed scan: d = ((dx*dx + dy*dy) + dz*dz), exact rn order
        float bd = -1.0f;
#pragma unroll
        for (int j = 0; j < FPS_PR; j++) {
            const uint64_t dx2 = add2(PX[j], ncx2);
            const uint64_t dy2 = add2(PY[j], ncy2);
            const uint64_t dz2 = add2(PZ[j], ncz2);
            const uint64_t dd =
                add2(add2(mul2(dx2, dx2), mul2(dy2, dy2)), mul2(dz2, dz2));
            float d0, d1; unpack2(dd, d0, d1);
            dist[2 * j]     = fminf(dist[2 * j],     d0);
            dist[2 * j + 1] = fminf(dist[2 * j + 1], d1);
            bd = fmaxf(bd, dist[2 * j]);
            bd = fmaxf(bd, dist[2 * j + 1]);
        }

        // ---- warp bfly max
#pragma unroll
        for (int off = 16; off; off >>= 1)
            bd = fmaxf(bd, __shfl_xor_sync(0xffffffffu, bd, off));
        if (lane == 0) s_warp[warp] = bd;
        if (t == 0) s_idx = 0xffffffffu;
        __syncthreads();

        // ---- block max (every warp reduces the 32 warp maxima)
        float ctabd = s_warp[lane];
#pragma unroll
        for (int off = 16; off; off >>= 1)
            ctabd = fmaxf(ctabd, __shfl_xor_sync(0xffffffffu, ctabd, off));

        // ---- rare candidate warps: first index (min gi) via smem atomicMin
        if (bd == ctabd) {
            unsigned mygi = 0xffffffffu;
#pragma unroll
            for (int i = 0; i < FPS_PT; i++)
                if (dist[i] == ctabd) mygi = min(mygi, (unsigned)(gi0 + i * FPS_T));
            atomicMin(&s_idx, mygi);
        }
        __syncthreads();

        const unsigned widx = s_idx;
        if (bd == ctabd) {
#pragma unroll
            for (int i = 0; i < FPS_PT; i++) {
                if ((unsigned)(gi0 + i * FPS_T) == widx) {
                    float x0, x1, y0, y1, z0, z1;
                    unpack2(PX[i >> 1], x0, x1);
                    unpack2(PY[i >> 1], y0, y1);
                    unpack2(PZ[i >> 1], z0, z1);
                    s_cand[0] = (i & 1) ? x1 : x0;
                    s_cand[1] = (i & 1) ? y1 : y0;
                    s_cand[2] = (i & 1) ? z1 : z0;
                }
            }
        }
        __syncthreads();

        // ---- cross-CTA exchange (warp0 only), double-buffered slots+mbarrier
        const int b = k & 1;
        if (warp == 0) {
            if (lane < FPS_CL) {
                const unsigned db = __float_as_uint(ctabd);
                const unsigned xb = __float_as_uint(s_cand[0]);
                const unsigned yb = __float_as_uint(s_cand[1]);
                const unsigned zb = __float_as_uint(s_cand[2]);
                const uint32_t slot_loc =
                    (uint32_t)__cvta_generic_to_shared(&s_slot4[b][rank]);
                const uint32_t zloc =
                    (uint32_t)__cvta_generic_to_shared(&s_slotz[b][rank]);
                const uint32_t barloc =
                    (uint32_t)__cvta_generic_to_shared(&s_mbar[b]);
                const uint32_t slot_rem = mapa_u32(slot_loc, (uint32_t)lane);
                const uint32_t z_rem    = mapa_u32(zloc,    (uint32_t)lane);
                const uint32_t bar_rem  = mapa_u32(barloc,  (uint32_t)lane);
                st_cluster_v4(slot_rem, db, widx, xb, yb);
                st_cluster_b32(z_rem, zb);
                mbar_arrive_rel_cluster(bar_rem);
            }
            mbar_wait_acq_cluster((uint32_t)__cvta_generic_to_shared(&s_mbar[b]),
                                  (unsigned)((k >> 1) & 1));

            const int l = lane & (FPS_CL - 1);
            const uint4 sl = s_slot4[b][l];
            const float slz = s_slotz[b][l];
            unsigned long long key =
                ((unsigned long long)sl.x << 32) | (unsigned)(~sl.y);
            const unsigned long long mykey = key;
#pragma unroll
            for (int off = 4; off; off >>= 1) {
                unsigned long long ok = __shfl_xor_sync(0xffffffffu, key, off);
                if (ok > key) key = ok;
            }
            const unsigned mask =
                __ballot_sync(0xffffffffu, mykey == key) & ((1u << FPS_CL) - 1u);
            const int src = __ffs(mask) - 1;
            const float wx = __shfl_sync(0xffffffffu, __uint_as_float(sl.z), src);
            const float wy = __shfl_sync(0xffffffffu, __uint_as_float(sl.w), src);
            const float wz = __shfl_sync(0xffffffffu, slz, src);
            if (lane == 0) { s_cent[0] = wx; s_cent[1] = wy; s_cent[2] = wz; }
            if (rank == 0 && lane == 1) {
                float* gs = &g_seeds[(batch * NSEED + k + 1) * 3];
                gs[0] = wx; gs[1] = wy; gs[2] = wz;
            }
        }
        __syncthreads();
    }
    cluster_sync_all();
}

// ---------------------------------------------------------------------------
// Kernel 2: den[b][s] = sum_n relu(r^2 - (|s|^2 + |p|^2 - 2 s.p)),
// then the LAST CTA computes the final variance with a LANE-PARALLEL tail
// (32 lanes x 5 vectorized ldcg each, two shfl pair-combines, butterfly sum
// -- replaces R11's serial 80-load tail that cost ~9us).
// Hot loop identical to the measured-10.6us R10/R14 den.
// ---------------------------------------------------------------------------
__global__ void __launch_bounds__(DEN_T)
den_kernel(const float* __restrict__ pcs, float* __restrict__ out)
{
    const int batch = blockIdx.y;
    const int chunk = blockIdx.x;
    const int t = threadIdx.x;

    __shared__ float4 ss[NSEED];
    __shared__ bool s_last;
    if (t < NSEED) {
        const float* gs = &g_seeds[(batch * NSEED + t) * 3];
        const float sx = gs[0], sy = gs[1], sz = gs[2];
        const float sn = sx * sx + sy * sy + sz * sz;
        ss[t] = make_float4(2.0f * sx, 2.0f * sy, 2.0f * sz, RAD2 - sn);
    }
    __syncthreads();

    const float* base = pcs + (size_t)batch * NPTS * 3;
    const int p0 = (chunk * DEN_T + t) * DEN_PT;     // 8 consecutive points

    // 6 x float4 = 24 floats = 8 points (vectorized, aligned)
    const float4* fp = reinterpret_cast<const float4*>(base + (size_t)p0 * 3);
    float f[DEN_PT * 3];
#pragma unroll
    for (int i = 0; i < (DEN_PT * 3) / 4; i++) {
        const float4 v = __ldg(&fp[i]);
        f[4 * i + 0] = v.x; f[4 * i + 1] = v.y;
        f[4 * i + 2] = v.z; f[4 * i + 3] = v.w;
    }

    uint64_t X2[DEN_PRR], Y2[DEN_PRR], Z2[DEN_PRR], NPN2[DEN_PRR];
#pragma unroll
    for (int j = 0; j < DEN_PRR; j++) {
        const float x0 = f[6 * j + 0], y0 = f[6 * j + 1], z0 = f[6 * j + 2];
        const float x1 = f[6 * j + 3], y1 = f[6 * j + 4], z1 = f[6 * j + 5];
        X2[j] = pack2(x0, x1);
        Y2[j] = pack2(y0, y1);
        Z2[j] = pack2(z0, z1);
        const float pn0 = fmaf(z0, z0, fmaf(y0, y0, x0 * x0));
        const float pn1 = fmaf(z1, z1, fmaf(y1, y1, x1 * x1));
        NPN2[j] = pack2(-pn0, -pn1);
    }

#pragma unroll 2
    for (int s = 0; s < NSEED; s++) {
        const float4 q = ss[s];
        const uint64_t qx2 = pack2(q.x, q.x);
        const uint64_t qy2 = pack2(q.y, q.y);
        const uint64_t qz2 = pack2(q.z, q.z);
        const uint64_t qw2 = pack2(q.w, q.w);
        float acc = 0.0f;
#pragma unroll
        for (int j = 0; j < DEN_PRR; j++) {
            uint64_t v = add2(qw2, NPN2[j]);
            v = fma2(X2[j], qx2, v);
            v = fma2(Y2[j], qy2, v);
            v = fma2(Z2[j], qz2, v);
            float v0, v1; unpack2(v, v0, v1);
            acc += fmaxf(v0, 0.0f);
            acc += fmaxf(v1, 0.0f);
        }
        if (acc != 0.0f) atomicAdd(&g_den[batch * NSEED + s], acc);
    }

    // ---- last-CTA-done: lane-parallel fused variance
    __syncthreads();
    if (t == 0) {
        __threadfence();
        s_last = (atomicAdd(&g_done, 1u) == DEN_CTAS - 1);
    }
    __syncthreads();
    if (s_last && t < 32) {
        __threadfence();                       // acquire side of the counter
        const int b = t >> 1;                  // batch 0..15
        const int h = t & 1;                   // half: seeds [0,20) or [20,40)
        // 20 contiguous floats = 5 x float4 (16B-aligned: offsets 160b+80h)
        const float4* p =
            reinterpret_cast<const float4*>(&g_den[b * NSEED + h * 20]);
        float vals[20];
#pragma unroll
        for (int i = 0; i < 5; i++) {
            const float4 v = __ldcg(&p[i]);
            vals[4 * i + 0] = v.x; vals[4 * i + 1] = v.y;
            vals[4 * i + 2] = v.z; vals[4 * i + 3] = v.w;
        }
        float s = 0.0f;
#pragma unroll
        for (int i = 0; i < 20; i++) s += vals[i];
        s += __shfl_xor_sync(0xffffffffu, s, 1);        // batch sum (both halves)
        const float m = s * (1.0f / NSEED);
        float q = 0.0f;
#pragma unroll
        for (int i = 0; i < 20; i++) {
            const float e = vals[i] - m;
            q += e * e;
        }
        q += __shfl_xor_sync(0xffffffffu, q, 1);        // batch sum of squares
        float v = (h == 0) ? q * (1.0f / (NSEED - 1)) : 0.0f;
#pragma unroll
        for (int off = 16; off; off >>= 1)
            v += __shfl_xor_sync(0xffffffffu, v, off);  // sum of 16 batch vars
        if (t == 0) out[0] = v * (1.0f / NB);
    }
}

// ---------------------------------------------------------------------------
extern "C" void kernel_launch(void* const* d_in, const int* in_sizes, int n_in,
                              void* d_out, int out_size)
{
    const float* pcs = (const float*)d_in[0];
    (void)in_sizes; (void)n_in; (void)out_size;

    fps_kernel<<<NB * FPS_CL, FPS_T>>>(pcs);
    den_kernel<<<dim3(DEN_CHUNKS, NB), DEN_T>>>(pcs, (float*)d_out);
}

// round 16
// speedup vs baseline: 1.5422x; 1.5422x over previous
#include <cuda_runtime.h>
#include <cooperative_groups.h>
#include <cstdint>

namespace cg = cooperative_groups;

#define NB    16
#define NPTS  65536
#define NSEED 40
#define RAD2  0.0025f

#define FPS_CL 8
#define FPS_T  1024
#define FPS_PT 8                 // NPTS / (FPS_CL * FPS_T)
#define FPS_PR (FPS_PT / 2)

#define DEN_T      256
#define DEN_PT     8             // consecutive points per thread
#define DEN_PRR    (DEN_PT / 2)
#define DEN_CHUNKS (NPTS / (DEN_T * DEN_PT))   // 32

__device__ float g_seeds[NB * NSEED * 3];
__device__ float g_den[NB * NSEED];

// ---------------- f32x2 packed helpers (element-wise rn => bitwise == scalar)
__device__ __forceinline__ uint64_t pack2(float lo, float hi) {
    uint64_t r; asm("mov.b64 %0, {%1, %2};" : "=l"(r) : "f"(lo), "f"(hi)); return r;
}
__device__ __forceinline__ void unpack2(uint64_t v, float& lo, float& hi) {
    asm("mov.b64 {%0, %1}, %2;" : "=f"(lo), "=f"(hi) : "l"(v));
}
__device__ __forceinline__ uint64_t add2(uint64_t a, uint64_t b) {
    uint64_t r; asm("add.rn.f32x2 %0, %1, %2;" : "=l"(r) : "l"(a), "l"(b)); return r;
}
__device__ __forceinline__ uint64_t mul2(uint64_t a, uint64_t b) {
    uint64_t r; asm("mul.rn.f32x2 %0, %1, %2;" : "=l"(r) : "l"(a), "l"(b)); return r;
}
__device__ __forceinline__ uint64_t fma2(uint64_t a, uint64_t b, uint64_t c) {
    uint64_t r; asm("fma.rn.f32x2 %0, %1, %2, %3;" : "=l"(r) : "l"(a), "l"(b), "l"(c)); return r;
}

// ---------------- cluster / mbarrier helpers
__device__ __forceinline__ uint32_t ctarank() {
    uint32_t r; asm("mov.u32 %0, %%cluster_ctarank;" : "=r"(r)); return r;
}
__device__ __forceinline__ uint32_t mapa_u32(uint32_t sa, uint32_t rank) {
    uint32_t r; asm("mapa.shared::cluster.u32 %0, %1, %2;" : "=r"(r) : "r"(sa), "r"(rank));
    return r;
}
__device__ __forceinline__ void st_cluster_v4(uint32_t a, uint32_t x, uint32_t y,
                                              uint32_t z, uint32_t w) {
    asm volatile("st.shared::cluster.v4.b32 [%0], {%1,%2,%3,%4};"
                 :: "r"(a), "r"(x), "r"(y), "r"(z), "r"(w) : "memory");
}
__device__ __forceinline__ void st_cluster_b32(uint32_t a, uint32_t v) {
    asm volatile("st.shared::cluster.b32 [%0], %1;" :: "r"(a), "r"(v) : "memory");
}
__device__ __forceinline__ void mbar_init(uint32_t a, uint32_t cnt) {
    asm volatile("mbarrier.init.shared.b64 [%0], %1;" :: "r"(a), "r"(cnt) : "memory");
}
__device__ __forceinline__ void mbar_arrive_rel_cluster(uint32_t a) {
    asm volatile("mbarrier.arrive.release.cluster.shared::cluster.b64 _, [%0];"
                 :: "r"(a) : "memory");
}
__device__ __forceinline__ void mbar_wait_acq_cluster(uint32_t a, uint32_t parity) {
    asm volatile(
        "{\n\t.reg .pred P;\n\t"
        "WL_%=:\n\t"
        "mbarrier.try_wait.parity.acquire.cluster.shared::cta.b64 P, [%0], %1, 0x989680;\n\t"
        "@!P bra WL_%=;\n\t"
        "}" :: "r"(a), "r"(parity) : "memory");
}
__device__ __forceinline__ void cluster_sync_all() {
    asm volatile("barrier.cluster.arrive.aligned;" ::: "memory");
    asm volatile("barrier.cluster.wait.aligned;" ::: "memory");
}

// ---------------------------------------------------------------------------
// Kernel 1: farthest point sampling — the best-measured (R2/R10/R14,
// 103-104us, reproduced 3x) protocol, verbatim.
// 8-CTA cluster per batch, 1024 thr/CTA, 8 pts/thread register-resident
// packed f32x2 (element-wise rn => bitwise == reference scalar order).
// Per step: packed scan -> warp bfly max -> block max (all warps) ->
// candidate atomicMin first-index -> candidate publishes xyz -> warp0 lanes
// 0..7 parallel DSMEM broadcast + mbar arrive -> warp0 waits once, reduces
// 8 slots, writes s_cent + g_seeds -> barrier.
// Tie-break: u64 key (distbits<<32)|~gi, max => first index == jnp.argmax.
// ---------------------------------------------------------------------------
__global__ void __cluster_dims__(FPS_CL, 1, 1) __launch_bounds__(FPS_T, 1)
fps_kernel(const float* __restrict__ pcs)
{
    const uint32_t rank = ctarank();
    const int batch = blockIdx.x / FPS_CL;
    const int t = threadIdx.x;
    const int warp = t >> 5, lane = t & 31;

    __shared__ float s_warp[32];
    __shared__ unsigned s_idx;
    __shared__ float s_cand[3];
    __shared__ float s_cent[3];
    __shared__ __align__(16) uint4 s_slot4[2][FPS_CL];   // {distbits, gi, xbits, ybits}
    __shared__ float s_slotz[2][FPS_CL];
    __shared__ __align__(8) unsigned long long s_mbar[2];

    const float* base = pcs + (size_t)batch * NPTS * 3;
    const int gi0 = (int)rank * (FPS_T * FPS_PT) + t;

    // load points, pack pairs (2j, 2j+1)
    float lx[FPS_PT], ly[FPS_PT], lz[FPS_PT];
#pragma unroll
    for (int i = 0; i < FPS_PT; i++) {
        const int gi = gi0 + i * FPS_T;
        lx[i] = base[gi * 3 + 0];
        ly[i] = base[gi * 3 + 1];
        lz[i] = base[gi * 3 + 2];
    }
    uint64_t PX[FPS_PR], PY[FPS_PR], PZ[FPS_PR];
    float dist[FPS_PT];
#pragma unroll
    for (int j = 0; j < FPS_PR; j++) {
        PX[j] = pack2(lx[2 * j], lx[2 * j + 1]);
        PY[j] = pack2(ly[2 * j], ly[2 * j + 1]);
        PZ[j] = pack2(lz[2 * j], lz[2 * j + 1]);
    }
#pragma unroll
    for (int i = 0; i < FPS_PT; i++) dist[i] = 1e10f;

    if (t == 0) {
        mbar_init((uint32_t)__cvta_generic_to_shared(&s_mbar[0]), FPS_CL);
        mbar_init((uint32_t)__cvta_generic_to_shared(&s_mbar[1]), FPS_CL);
        s_cent[0] = base[0]; s_cent[1] = base[1]; s_cent[2] = base[2];
    }
    if (rank == 0) {
        if (t < NSEED) g_den[batch * NSEED + t] = 0.0f;
        if (t == 0) {
            g_seeds[(batch * NSEED) * 3 + 0] = base[0];
            g_seeds[(batch * NSEED) * 3 + 1] = base[1];
            g_seeds[(batch * NSEED) * 3 + 2] = base[2];
        }
    }
    __syncthreads();
    cluster_sync_all();   // all mbarriers initialized cluster-wide

#pragma unroll 1
    for (int k = 0; k < NSEED - 1; k++) {
        const float cx = s_cent[0], cy = s_cent[1], cz = s_cent[2];
        const uint64_t ncx2 = pack2(-cx, -cx);
        const uint64_t ncy2 = pack2(-cy, -cy);
        const uint64_t ncz2 = pack2(-cz, -cz);

        // ---- packed scan: d = ((dx*dx + dy*dy) + dz*dz), exact rn order
        float bd = -1.0f;
#pragma unroll
        for (int j = 0; j < FPS_PR; j++) {
            const uint64_t dx2 = add2(PX[j], ncx2);
            const uint64_t dy2 = add2(PY[j], ncy2);
            const uint64_t dz2 = add2(PZ[j], ncz2);
            const uint64_t dd =
                add2(add2(mul2(dx2, dx2), mul2(dy2, dy2)), mul2(dz2, dz2));
            float d0, d1; unpack2(dd, d0, d1);
            dist[2 * j]     = fminf(dist[2 * j],     d0);
            dist[2 * j + 1] = fminf(dist[2 * j + 1], d1);
            bd = fmaxf(bd, dist[2 * j]);
            bd = fmaxf(bd, dist[2 * j + 1]);
        }

        // ---- warp bfly max
#pragma unroll
        for (int off = 16; off; off >>= 1)
            bd = fmaxf(bd, __shfl_xor_sync(0xffffffffu, bd, off));
        if (lane == 0) s_warp[warp] = bd;
        if (t == 0) s_idx = 0xffffffffu;
        __syncthreads();

        // ---- block max (every warp reduces the 32 warp maxima)
        float ctabd = s_warp[lane];
#pragma unroll
        for (int off = 16; off; off >>= 1)
            ctabd = fmaxf(ctabd, __shfl_xor_sync(0xffffffffu, ctabd, off));

        // ---- rare candidate warps: first index (min gi) via smem atomicMin
        if (bd == ctabd) {
            unsigned mygi = 0xffffffffu;
#pragma unroll
            for (int i = 0; i < FPS_PT; i++)
                if (dist[i] == ctabd) mygi = min(mygi, (unsigned)(gi0 + i * FPS_T));
            atomicMin(&s_idx, mygi);
        }
        __syncthreads();

        const unsigned widx = s_idx;
        if (bd == ctabd) {
#pragma unroll
            for (int i = 0; i < FPS_PT; i++) {
                if ((unsigned)(gi0 + i * FPS_T) == widx) {
                    float x0, x1, y0, y1, z0, z1;
                    unpack2(PX[i >> 1], x0, x1);
                    unpack2(PY[i >> 1], y0, y1);
                    unpack2(PZ[i >> 1], z0, z1);
                    s_cand[0] = (i & 1) ? x1 : x0;
                    s_cand[1] = (i & 1) ? y1 : y0;
                    s_cand[2] = (i & 1) ? z1 : z0;
                }
            }
        }
        __syncthreads();

        // ---- cross-CTA exchange (warp0 only), double-buffered slots+mbarrier
        const int b = k & 1;
        if (warp == 0) {
            if (lane < FPS_CL) {
                const unsigned db = __float_as_uint(ctabd);
                const unsigned xb = __float_as_uint(s_cand[0]);
                const unsigned yb = __float_as_uint(s_cand[1]);
                const unsigned zb = __float_as_uint(s_cand[2]);
                const uint32_t slot_loc =
                    (uint32_t)__cvta_generic_to_shared(&s_slot4[b][rank]);
                const uint32_t zloc =
                    (uint32_t)__cvta_generic_to_shared(&s_slotz[b][rank]);
                const uint32_t barloc =
                    (uint32_t)__cvta_generic_to_shared(&s_mbar[b]);
                const uint32_t slot_rem = mapa_u32(slot_loc, (uint32_t)lane);
                const uint32_t z_rem    = mapa_u32(zloc,    (uint32_t)lane);
                const uint32_t bar_rem  = mapa_u32(barloc,  (uint32_t)lane);
                st_cluster_v4(slot_rem, db, widx, xb, yb);
                st_cluster_b32(z_rem, zb);
                mbar_arrive_rel_cluster(bar_rem);
            }
            mbar_wait_acq_cluster((uint32_t)__cvta_generic_to_shared(&s_mbar[b]),
                                  (unsigned)((k >> 1) & 1));

            const int l = lane & (FPS_CL - 1);
            const uint4 sl = s_slot4[b][l];
            const float slz = s_slotz[b][l];
            unsigned long long key =
                ((unsigned long long)sl.x << 32) | (unsigned)(~sl.y);
            const unsigned long long mykey = key;
#pragma unroll
            for (int off = 4; off; off >>= 1) {
                unsigned long long ok = __shfl_xor_sync(0xffffffffu, key, off);
                if (ok > key) key = ok;
            }
            const unsigned mask =
                __ballot_sync(0xffffffffu, mykey == key) & ((1u << FPS_CL) - 1u);
            const int src = __ffs(mask) - 1;
            const float wx = __shfl_sync(0xffffffffu, __uint_as_float(sl.z), src);
            const float wy = __shfl_sync(0xffffffffu, __uint_as_float(sl.w), src);
            const float wz = __shfl_sync(0xffffffffu, slz, src);
            if (lane == 0) { s_cent[0] = wx; s_cent[1] = wy; s_cent[2] = wz; }
            if (rank == 0 && lane == 1) {
                float* gs = &g_seeds[(batch * NSEED + k + 1) * 3];
                gs[0] = wx; gs[1] = wy; gs[2] = wz;
            }
        }
        __syncthreads();
    }
    cluster_sync_all();
}

// ---------------------------------------------------------------------------
// Kernel 2: den[b][s] = sum_n relu(r^2 - (|s|^2 + |p|^2 - 2 s.p))
// Each thread: 8 CONSECUTIVE points via 6x LDG.128 (16B-aligned since
// p0*12B with p0 % 8 == 0), packed f32x2 pairs, 40-seed FMA sweep,
// sparse predicated atomicAdd.
// ---------------------------------------------------------------------------
__global__ void __launch_bounds__(DEN_T)
den_kernel(const float* __restrict__ pcs)
{
    const int batch = blockIdx.y;
    const int chunk = blockIdx.x;
    const int t = threadIdx.x;

    __shared__ float4 ss[NSEED];
    if (t < NSEED) {
        const float* gs = &g_seeds[(batch * NSEED + t) * 3];
        const float sx = gs[0], sy = gs[1], sz = gs[2];
        const float sn = sx * sx + sy * sy + sz * sz;
        ss[t] = make_float4(2.0f * sx, 2.0f * sy, 2.0f * sz, RAD2 - sn);
    }
    __syncthreads();

    const float* base = pcs + (size_t)batch * NPTS * 3;
    const int p0 = (chunk * DEN_T + t) * DEN_PT;     // 8 consecutive points

    // 6 x float4 = 24 floats = 8 points (vectorized, aligned)
    const float4* fp = reinterpret_cast<const float4*>(base + (size_t)p0 * 3);
    float f[DEN_PT * 3];
#pragma unroll
    for (int i = 0; i < (DEN_PT * 3) / 4; i++) {
        const float4 v = __ldg(&fp[i]);
        f[4 * i + 0] = v.x; f[4 * i + 1] = v.y;
        f[4 * i + 2] = v.z; f[4 * i + 3] = v.w;
    }

    uint64_t X2[DEN_PRR], Y2[DEN_PRR], Z2[DEN_PRR], NPN2[DEN_PRR];
#pragma unroll
    for (int j = 0; j < DEN_PRR; j++) {
        const float x0 = f[6 * j + 0], y0 = f[6 * j + 1], z0 = f[6 * j + 2];
        const float x1 = f[6 * j + 3], y1 = f[6 * j + 4], z1 = f[6 * j + 5];
        X2[j] = pack2(x0, x1);
        Y2[j] = pack2(y0, y1);
        Z2[j] = pack2(z0, z1);
        const float pn0 = fmaf(z0, z0, fmaf(y0, y0, x0 * x0));
        const float pn1 = fmaf(z1, z1, fmaf(y1, y1, x1 * x1));
        NPN2[j] = pack2(-pn0, -pn1);
    }

#pragma unroll 2
    for (int s = 0; s < NSEED; s++) {
        const float4 q = ss[s];
        const uint64_t qx2 = pack2(q.x, q.x);
        const uint64_t qy2 = pack2(q.y, q.y);
        const uint64_t qz2 = pack2(q.z, q.z);
        const uint64_t qw2 = pack2(q.w, q.w);
        float acc = 0.0f;
#pragma unroll
        for (int j = 0; j < DEN_PRR; j++) {
            uint64_t v = add2(qw2, NPN2[j]);
            v = fma2(X2[j], qx2, v);
            v = fma2(Y2[j], qy2, v);
            v = fma2(Z2[j], qz2, v);
            float v0, v1; unpack2(v, v0, v1);
            acc += fmaxf(v0, 0.0f);
            acc += fmaxf(v1, 0.0f);
        }
        if (acc != 0.0f) atomicAdd(&g_den[batch * NSEED + s], acc);
    }
}

// ---------------------------------------------------------------------------
// Kernel 3: out = mean_b( var_{ddof=1,s}( den[b][s] ) )
// ---------------------------------------------------------------------------
__global__ void var_kernel(float* __restrict__ out)
{
    const int lane = threadIdx.x;
    float v = 0.0f;
    if (lane < NB) {
        const float* d = &g_den[lane * NSEED];
        float s = 0.0f;
        for (int i = 0; i < NSEED; i++) s += d[i];
        const float m = s * (1.0f / NSEED);
        float q = 0.0f;
        for (int i = 0; i < NSEED; i++) {
            const float e = d[i] - m;
            q += e * e;
        }
        v = q * (1.0f / (NSEED - 1));
    }
#pragma unroll
    for (int off = 8; off; off >>= 1)
        v += __shfl_down_sync(0xffffffffu, v, off);
    if (lane == 0) out[0] = v * (1.0f / NB);
}

// ---------------------------------------------------------------------------
extern "C" void kernel_launch(void* const* d_in, const int* in_sizes, int n_in,
                              void* d_out, int out_size)
{
    const float* pcs = (const float*)d_in[0];
    (void)in_sizes; (void)n_in; (void)out_size;

    fps_kernel<<<NB * FPS_CL, FPS_T>>>(pcs);
    den_kernel<<<dim3(DEN_CHUNKS, NB), DEN_T>>>(pcs);
    var_kernel<<<1, 32>>>((float*)d_out);
}